// round 7
// baseline (speedup 1.0000x reference)
#include <cuda_runtime.h>
#include <cstdint>

#define C 128
#define KC 27
#define NLOW_MAX 50000
#define NHIGH_MAX 200000
#define E_MAX 1000000
#define EPAD_MAX (E_MAX + KC * 128)
#define MAXBLK 2048
#define SCAN_ELEMS 2048
#define NBLK_MAX ((NHIGH_MAX + SCAN_ELEMS - 1) / SCAN_ELEMS)   // 98

// Packed per-row tf32 layout: row r, word tg*32 + q*4 + w holds col c = 16q + 4w + tg
__device__ unsigned g_xr[(size_t)NLOW_MAX * C];      // 25.6 MB
__device__ unsigned g_wr[(size_t)KC * C * C];        // 1.77 MB
__device__ float    g_msg[(size_t)E_MAX * C];        // 512 MB

__device__ int g_js[EPAD_MAX];
__device__ int g_dst[EPAD_MAX];
__device__ int g_kcnt[KC];
__device__ int g_kcur[KC];
__device__ int g_poffs[KC];
__device__ int g_blk_k[MAXBLK];
__device__ int g_blk_c0[MAXBLK];
__device__ int g_blk_nc[MAXBLK];
__device__ int g_nblocks;

__device__ int g_icnt[NHIGH_MAX];
__device__ int g_istart[NHIGH_MAX];
__device__ int g_icur[NHIGH_MAX];
__device__ int g_bsum[NBLK_MAX + 1];

__device__ __forceinline__ unsigned f2tf32(float x) {
    unsigned u;
    asm("cvt.rna.tf32.f32 %0, %1;" : "=r"(u) : "f"(x));
    return u;
}

__device__ __forceinline__ void mma_tf32(float c[4],
                                         unsigned a0, unsigned a1, unsigned a2, unsigned a3,
                                         unsigned b0, unsigned b1) {
    asm volatile(
        "mma.sync.aligned.m16n8k8.row.col.f32.tf32.tf32.f32 "
        "{%0,%1,%2,%3}, {%4,%5,%6,%7}, {%8,%9}, {%0,%1,%2,%3};\n"
        : "+f"(c[0]), "+f"(c[1]), "+f"(c[2]), "+f"(c[3])
        : "r"(a0), "r"(a1), "r"(a2), "r"(a3), "r"(b0), "r"(b1));
}

__device__ __forceinline__ void cpa16(unsigned saddr, const void* gptr) {
    asm volatile("cp.async.cg.shared.global [%0], [%1], 16;"
                 :: "r"(saddr), "l"(gptr) : "memory");
}

// ---- pre-pass: pack X / W to tf32 ----
__global__ void pack_x_kernel(const float* __restrict__ X, int N) {
    int idx = blockIdx.x * blockDim.x + threadIdx.x;
    if (idx >= N * 32) return;
    int row = idx >> 5;
    int c0 = (idx & 31) << 2;
    float4 f = *(const float4*)(X + (size_t)row * C + c0);
    int w = (c0 >> 2) & 3, q = c0 >> 4;
    unsigned* dst = g_xr + (size_t)row * C + q * 4 + w;
    dst[0]  = f2tf32(f.x);
    dst[32] = f2tf32(f.y);
    dst[64] = f2tf32(f.z);
    dst[96] = f2tf32(f.w);
}

__global__ void pack_w_kernel(const float* __restrict__ W) {
    int idx = blockIdx.x * blockDim.x + threadIdx.x;
    if (idx >= KC * 128 * 32) return;
    int c0 = (idx & 31) << 2;
    int row = idx >> 5;
    float4 f = *(const float4*)(W + (size_t)row * C + c0);
    int w = (c0 >> 2) & 3, q = c0 >> 4;
    unsigned* dst = g_wr + (size_t)row * C + q * 4 + w;
    dst[0]  = f2tf32(f.x);
    dst[32] = f2tf32(f.y);
    dst[64] = f2tf32(f.z);
    dst[96] = f2tf32(f.w);
}

// ---- init: pads + zero counters ----
__global__ void zinit_kernel(int epad, int NH) {
    int idx = blockIdx.x * blockDim.x + threadIdx.x;
    if (idx < epad) { g_js[idx] = 0; g_dst[idx] = -1; }
    if (idx < NH) g_icnt[idx] = 0;
    if (idx < KC) g_kcnt[idx] = 0;
}

// ---- histograms: k (smem) + i (spread atomics) in one pass ----
__global__ void hist_kernel(const int* __restrict__ ih, const int* __restrict__ kc, int E) {
    __shared__ int h[KC];
    int tid = threadIdx.x;
    if (tid < KC) h[tid] = 0;
    __syncthreads();
    for (int e = blockIdx.x * blockDim.x + tid; e < E; e += gridDim.x * blockDim.x) {
        atomicAdd(&g_icnt[ih[e]], 1);
        atomicAdd(&h[kc[e]], 1);
    }
    __syncthreads();
    if (tid < KC) atomicAdd(&g_kcnt[tid], h[tid]);
}

// ---- k offsets + phase-1 block descriptors ----
__global__ void koffs_kernel() {
    if (threadIdx.x != 0) return;
    int off = 0, nb = 0;
    for (int k = 0; k < KC; k++) {
        g_poffs[k] = off;
        g_kcur[k] = off;
        int ch = (g_kcnt[k] + 127) >> 7;
        off += ch << 7;
        for (int q = 0; q < ch; q += 4) {
            g_blk_k[nb] = k;
            g_blk_c0[nb] = q;
            g_blk_nc[nb] = (ch - q) < 4 ? (ch - q) : 4;
            nb++;
        }
    }
    g_nblocks = nb;
}

// ---- prefix scan over i-counts (3 small kernels) ----
__global__ void scan1_kernel(int NH) {              // 512 threads
    int tid = threadIdx.x;
    int base = blockIdx.x * SCAN_ELEMS + tid * 4;
    int s = 0;
#pragma unroll
    for (int u = 0; u < 4; u++) {
        int i = base + u;
        if (i < NH) s += g_icnt[i];
    }
#pragma unroll
    for (int o = 16; o; o >>= 1) s += __shfl_down_sync(~0u, s, o);
    __shared__ int ws[16];
    if ((tid & 31) == 0) ws[tid >> 5] = s;
    __syncthreads();
    if (tid == 0) {
        int t = 0;
        for (int w = 0; w < 16; w++) t += ws[w];
        g_bsum[blockIdx.x] = t;
    }
}

__global__ void scan2_kernel(int nb) {              // 1 block, 128 threads
    __shared__ int sh[NBLK_MAX];
    int tid = threadIdx.x;
    if (tid < nb) sh[tid] = g_bsum[tid];
    __syncthreads();
    if (tid == 0) {
        int run = 0;
        for (int b = 0; b < nb; b++) { int t = sh[b]; sh[b] = run; run += t; }
    }
    __syncthreads();
    if (tid < nb) g_bsum[tid] = sh[tid];
}

__global__ void scan3_kernel(int NH) {              // 512 threads
    int tid = threadIdx.x;
    int lane = tid & 31, wid = tid >> 5;
    int base = blockIdx.x * SCAN_ELEMS + tid * 4;
    int v[4], ts = 0;
#pragma unroll
    for (int u = 0; u < 4; u++) {
        int i = base + u;
        v[u] = (i < NH) ? g_icnt[i] : 0;
        ts += v[u];
    }
    int incl = ts;
#pragma unroll
    for (int o = 1; o < 32; o <<= 1) {
        int n = __shfl_up_sync(~0u, incl, o);
        if (lane >= o) incl += n;
    }
    __shared__ int wtot[16], woff[16];
    if (lane == 31) wtot[wid] = incl;
    __syncthreads();
    if (tid == 0) {
        int run = 0;
        for (int w = 0; w < 16; w++) { int t = wtot[w]; woff[w] = run; run += t; }
    }
    __syncthreads();
    int pre = g_bsum[blockIdx.x] + woff[wid] + (incl - ts);
#pragma unroll
    for (int u = 0; u < 4; u++) {
        int i = base + u;
        if (i < NH) { g_istart[i] = pre; g_icur[i] = pre; pre += v[u]; }
    }
}

// ---- sort by k + assign i-rank destination ----
__global__ void sortrank_kernel(const int* __restrict__ ih, const int* __restrict__ jl,
                                const int* __restrict__ kc, int E) {
    int e = blockIdx.x * blockDim.x + threadIdx.x;
    if (e >= E) return;
    int k = kc[e];
    int pos = atomicAdd(&g_kcur[k], 1);
    int rank = atomicAdd(&g_icur[ih[e]], 1);
    g_js[pos] = jl[e];
    g_dst[pos] = rank;
}

// ---- phase 1: fused gather-GEMM -> msg[rank] (plain stores, no atomics) ----
#define ROW_STR 144
#define TG_STR 36
#define TILE_WORDS (128 * ROW_STR)
#define ACC_STR 136
#define SMEM_BYTES (3 * TILE_WORDS * 4)   // 221,184 B

__device__ __forceinline__ void stage_A(unsigned sbuf, int base, int tid) {
    int r = tid >> 2;
    int sub = tid & 3;
    int j = g_js[base + r];
    const unsigned* src = g_xr + (size_t)j * C + sub * 32;
    unsigned dst = sbuf + (r * ROW_STR + sub * TG_STR) * 4;
#pragma unroll
    for (int q = 0; q < 8; q++)
        cpa16(dst + q * 16, src + q * 4);
}

__global__ void __launch_bounds__(512, 1) phase1_kernel() {
    int b = blockIdx.x;
    if (b >= g_nblocks) return;
    extern __shared__ unsigned smem[];
    unsigned* Ws = smem;
    unsigned* Ab[2] = { smem + TILE_WORDS, smem + 2 * TILE_WORDS };
    const int tid = threadIdx.x;

    const int k  = g_blk_k[b];
    const int c0 = g_blk_c0[b];
    const int nc = g_blk_nc[b];
    const int pb = g_poffs[k];

    unsigned sW = (unsigned)__cvta_generic_to_shared(Ws);
    unsigned sA[2] = { (unsigned)__cvta_generic_to_shared(Ab[0]),
                       (unsigned)__cvta_generic_to_shared(Ab[1]) };

    {
        const unsigned* wsrc = g_wr + (size_t)k * C * C;
#pragma unroll
        for (int i = 0; i < 8; i++) {
            int cidx = tid + i * 512;
            int row = cidx >> 5, u = cidx & 31;
            int tg = u >> 3, q = u & 7;
            cpa16(sW + (row * ROW_STR + tg * TG_STR + q * 4) * 4,
                  wsrc + row * C + tg * 32 + q * 4);
        }
        stage_A(sA[0], pb + (c0 + 0) * 128, tid);
    }
    asm volatile("cp.async.commit_group;");
    if (nc > 1) stage_A(sA[1], pb + (c0 + 1) * 128, tid);
    asm volatile("cp.async.commit_group;");

    const int warp = tid >> 5, lane = tid & 31;
    const int g = lane >> 2, tg = lane & 3;
    const int rowBase = (warp >> 2) * 32;
    const int coBase  = (warp & 3) * 32;
    const int bOff = (coBase + g) * ROW_STR + tg * TG_STR;
    const int ntStride = (8 * ROW_STR) / 4;

    for (int t = 0; t < nc; t++) {
        asm volatile("cp.async.wait_group 1;" ::: "memory");
        __syncthreads();

        unsigned* Ax = Ab[t & 1];
        const uint4* A0 = (const uint4*)(Ax + (rowBase + g     ) * ROW_STR + tg * TG_STR);
        const uint4* A1 = (const uint4*)(Ax + (rowBase + g +  8) * ROW_STR + tg * TG_STR);
        const uint4* A2 = (const uint4*)(Ax + (rowBase + g + 16) * ROW_STR + tg * TG_STR);
        const uint4* A3 = (const uint4*)(Ax + (rowBase + g + 24) * ROW_STR + tg * TG_STR);
        const uint4* Bp = (const uint4*)(Ws + bOff);

        float acc[2][4][4];
#pragma unroll
        for (int mt = 0; mt < 2; mt++)
#pragma unroll
            for (int nt = 0; nt < 4; nt++) {
                acc[mt][nt][0] = 0.f; acc[mt][nt][1] = 0.f;
                acc[mt][nt][2] = 0.f; acc[mt][nt][3] = 0.f;
            }

#pragma unroll
        for (int q = 0; q < 8; q++) {
            uint4 a0 = A0[q];
            uint4 a1 = A1[q];
            uint4 a2 = A2[q];
            uint4 a3 = A3[q];
            uint4 b0 = Bp[0 * ntStride + q];
            uint4 b1 = Bp[1 * ntStride + q];
            uint4 b2 = Bp[2 * ntStride + q];
            uint4 b3 = Bp[3 * ntStride + q];
            mma_tf32(acc[0][0], a0.x, a1.x, a0.y, a1.y, b0.x, b0.y);
            mma_tf32(acc[0][1], a0.x, a1.x, a0.y, a1.y, b1.x, b1.y);
            mma_tf32(acc[0][2], a0.x, a1.x, a0.y, a1.y, b2.x, b2.y);
            mma_tf32(acc[0][3], a0.x, a1.x, a0.y, a1.y, b3.x, b3.y);
            mma_tf32(acc[1][0], a2.x, a3.x, a2.y, a3.y, b0.x, b0.y);
            mma_tf32(acc[1][1], a2.x, a3.x, a2.y, a3.y, b1.x, b1.y);
            mma_tf32(acc[1][2], a2.x, a3.x, a2.y, a3.y, b2.x, b2.y);
            mma_tf32(acc[1][3], a2.x, a3.x, a2.y, a3.y, b3.x, b3.y);
            mma_tf32(acc[0][0], a0.z, a1.z, a0.w, a1.w, b0.z, b0.w);
            mma_tf32(acc[0][1], a0.z, a1.z, a0.w, a1.w, b1.z, b1.w);
            mma_tf32(acc[0][2], a0.z, a1.z, a0.w, a1.w, b2.z, b2.w);
            mma_tf32(acc[0][3], a0.z, a1.z, a0.w, a1.w, b3.z, b3.w);
            mma_tf32(acc[1][0], a2.z, a3.z, a2.w, a3.w, b0.z, b0.w);
            mma_tf32(acc[1][1], a2.z, a3.z, a2.w, a3.w, b1.z, b1.w);
            mma_tf32(acc[1][2], a2.z, a3.z, a2.w, a3.w, b2.z, b2.w);
            mma_tf32(acc[1][3], a2.z, a3.z, a2.w, a3.w, b3.z, b3.w);
        }

        __syncthreads();
        float* As = (float*)Ax;
#pragma unroll
        for (int mt = 0; mt < 2; mt++) {
            int r0 = rowBase + mt * 16 + g;
#pragma unroll
            for (int nt = 0; nt < 4; nt++) {
                int co = coBase + nt * 8 + tg * 2;
                *(float2*)(As + r0 * ACC_STR + co) =
                    make_float2(acc[mt][nt][0], acc[mt][nt][1]);
                *(float2*)(As + (r0 + 8) * ACC_STR + co) =
                    make_float2(acc[mt][nt][2], acc[mt][nt][3]);
            }
        }
        __syncthreads();

        // write rows to msg[rank] — coalesced 512B stores, no atomics
        int baseE = pb + (c0 + t) * 128;
#pragma unroll
        for (int rr = 0; rr < 8; rr++) {
            int row = warp * 8 + rr;
            int dst = g_dst[baseE + row];
            if (dst >= 0) {
                float4 v = *(const float4*)(As + row * ACC_STR + lane * 4);
                *(float4*)(g_msg + (size_t)dst * C + lane * 4) = v;
            }
        }
        __syncthreads();

        if (t + 2 < nc) stage_A(sA[t & 1], pb + (c0 + t + 2) * 128, tid);
        asm volatile("cp.async.commit_group;");
    }
}

// ---- phase 2: segmented sum + bias (warp per output row) ----
__global__ void segsum_kernel(float* __restrict__ out, const float* __restrict__ bias,
                              int NH) {
    int gw = (blockIdx.x * blockDim.x + threadIdx.x) >> 5;
    int lane = threadIdx.x & 31;
    if (gw >= NH) return;
    int start = g_istart[gw];
    int cnt = g_icnt[gw];
    float4 acc = ((const float4*)bias)[lane];
    const float4* m = (const float4*)g_msg;
    int r = 0;
    for (; r + 4 <= cnt; r += 4) {
        float4 a = m[(size_t)(start + r)     * 32 + lane];
        float4 b = m[(size_t)(start + r + 1) * 32 + lane];
        float4 c = m[(size_t)(start + r + 2) * 32 + lane];
        float4 d = m[(size_t)(start + r + 3) * 32 + lane];
        acc.x += (a.x + b.x) + (c.x + d.x);
        acc.y += (a.y + b.y) + (c.y + d.y);
        acc.z += (a.z + b.z) + (c.z + d.z);
        acc.w += (a.w + b.w) + (c.w + d.w);
    }
    for (; r < cnt; r++) {
        float4 a = m[(size_t)(start + r) * 32 + lane];
        acc.x += a.x; acc.y += a.y; acc.z += a.z; acc.w += a.w;
    }
    ((float4*)out)[(size_t)gw * 32 + lane] = acc;
}

extern "C" void kernel_launch(void* const* d_in, const int* in_sizes, int n_in,
                              void* d_out, int out_size) {
    const float* x    = (const float*)d_in[0];
    const float* w    = (const float*)d_in[1];
    const float* bias = (const float*)d_in[2];
    const int* ih     = (const int*)d_in[3];
    const int* jl     = (const int*)d_in[4];
    const int* kc     = (const int*)d_in[5];
    float* out = (float*)d_out;

    const int Nlow = in_sizes[0] / C;
    const int E    = in_sizes[3];
    const int NH   = out_size / C;
    const int epad = E + KC * 128;
    const int nbScan = (NH + SCAN_ELEMS - 1) / SCAN_ELEMS;

    pack_x_kernel<<<(Nlow * 32 + 255) / 256, 256>>>(x, Nlow);
    pack_w_kernel<<<(KC * 128 * 32 + 255) / 256, 256>>>(w);

    int zmax = epad > NH ? epad : NH;
    zinit_kernel<<<(zmax + 255) / 256, 256>>>(epad, NH);
    hist_kernel<<<512, 256>>>(ih, kc, E);
    koffs_kernel<<<1, 32>>>();
    scan1_kernel<<<nbScan, 512>>>(NH);
    scan2_kernel<<<1, 128>>>(nbScan);
    scan3_kernel<<<nbScan, 512>>>(NH);
    sortrank_kernel<<<(E + 255) / 256, 256>>>(ih, jl, kc, E);

    cudaFuncSetAttribute(phase1_kernel, cudaFuncAttributeMaxDynamicSharedMemorySize,
                         SMEM_BYTES);
    phase1_kernel<<<MAXBLK, 512, SMEM_BYTES>>>();

    long long sthreads = (long long)NH * 32;
    segsum_kernel<<<(int)((sthreads + 255) / 256), 256>>>(out, bias, NH);
}

// round 8
// speedup vs baseline: 1.7711x; 1.7711x over previous
#include <cuda_runtime.h>
#include <cuda_fp16.h>
#include <cstdint>

#define C 128
#define KC 27
#define NLOW_MAX 50000
#define NLOW_PAD 50176                      // 392*128, padded for OOB-safe staging
#define NHIGH_MAX 200000
#define E_MAX 1000000
#define SCAN_ELEMS 2048
#define NBLK_MAX ((NHIGH_MAX + SCAN_ELEMS - 1) / SCAN_ELEMS)   // 98

// fp16 packed rows: 64 words/row; word w = tg*16 + kb*2 + h holds halves
// (c0, c0+1) with c0 = 16*kb + 2*tg + 8*h   (mma m16n8k16 fragment order)
__device__ unsigned g_xh[(size_t)NLOW_PAD * 64];       // 12.8 MB (zero-init pad)
__device__ unsigned g_wh[(size_t)KC * C * 64];         // 884 KB
__device__ __half2  g_y2[(size_t)KC * NLOW_MAX * 64];  // 345.6 MB

__device__ int g_jk[E_MAX];          // k*Nlow + j, sorted by destination i
__device__ int g_icnt[NHIGH_MAX];
__device__ int g_istart[NHIGH_MAX];
__device__ int g_icur[NHIGH_MAX];
__device__ int g_bsum[NBLK_MAX + 1];

__device__ __forceinline__ void mma_f16(float c[4],
                                        unsigned a0, unsigned a1, unsigned a2, unsigned a3,
                                        unsigned b0, unsigned b1) {
    asm volatile(
        "mma.sync.aligned.m16n8k16.row.col.f32.f16.f16.f32 "
        "{%0,%1,%2,%3}, {%4,%5,%6,%7}, {%8,%9}, {%0,%1,%2,%3};\n"
        : "+f"(c[0]), "+f"(c[1]), "+f"(c[2]), "+f"(c[3])
        : "r"(a0), "r"(a1), "r"(a2), "r"(a3), "r"(b0), "r"(b1));
}

__device__ __forceinline__ void cpa16(unsigned saddr, const void* gptr) {
    asm volatile("cp.async.cg.shared.global [%0], [%1], 16;"
                 :: "r"(saddr), "l"(gptr) : "memory");
}

// ---- pack X rows to fp16 fragment order ----
__global__ void pack_x_kernel(const float* __restrict__ X, int N) {
    int idx = blockIdx.x * blockDim.x + threadIdx.x;    // one word each
    if (idx >= N * 64) return;
    int row = idx >> 6, w = idx & 63;
    int tg = w >> 4, r2 = w & 15, kb = r2 >> 1, h = r2 & 1;
    int c0 = 16 * kb + 2 * tg + 8 * h;
    const float* src = X + (size_t)row * C + c0;
    __half2 v = __float22half2_rn(make_float2(src[0], src[1]));
    g_xh[idx] = *(unsigned*)&v;
}

__global__ void pack_w_kernel(const float* __restrict__ W) {
    int idx = blockIdx.x * blockDim.x + threadIdx.x;
    if (idx >= KC * C * 64) return;
    int row = idx >> 6, w = idx & 63;                   // row = k*128 + co
    int tg = w >> 4, r2 = w & 15, kb = r2 >> 1, h = r2 & 1;
    int c0 = 16 * kb + 2 * tg + 8 * h;
    const float* src = W + (size_t)row * C + c0;
    __half2 v = __float22half2_rn(make_float2(src[0], src[1]));
    g_wh[idx] = *(unsigned*)&v;
}

// ---- i-histogram machinery (verified in R7) ----
__global__ void zinit_kernel(int NH) {
    int idx = blockIdx.x * blockDim.x + threadIdx.x;
    if (idx < NH) g_icnt[idx] = 0;
}

__global__ void hist_kernel(const int* __restrict__ ih, int E) {
    for (int e = blockIdx.x * blockDim.x + threadIdx.x; e < E;
         e += gridDim.x * blockDim.x)
        atomicAdd(&g_icnt[ih[e]], 1);
}

__global__ void scan1_kernel(int NH) {
    int tid = threadIdx.x;
    int base = blockIdx.x * SCAN_ELEMS + tid * 4;
    int s = 0;
#pragma unroll
    for (int u = 0; u < 4; u++) {
        int i = base + u;
        if (i < NH) s += g_icnt[i];
    }
#pragma unroll
    for (int o = 16; o; o >>= 1) s += __shfl_down_sync(~0u, s, o);
    __shared__ int ws[16];
    if ((tid & 31) == 0) ws[tid >> 5] = s;
    __syncthreads();
    if (tid == 0) {
        int t = 0;
        for (int w = 0; w < 16; w++) t += ws[w];
        g_bsum[blockIdx.x] = t;
    }
}

__global__ void scan2_kernel(int nb) {
    __shared__ int sh[NBLK_MAX];
    int tid = threadIdx.x;
    if (tid < nb) sh[tid] = g_bsum[tid];
    __syncthreads();
    if (tid == 0) {
        int run = 0;
        for (int b = 0; b < nb; b++) { int t = sh[b]; sh[b] = run; run += t; }
    }
    __syncthreads();
    if (tid < nb) g_bsum[tid] = sh[tid];
}

__global__ void scan3_kernel(int NH) {
    int tid = threadIdx.x;
    int lane = tid & 31, wid = tid >> 5;
    int base = blockIdx.x * SCAN_ELEMS + tid * 4;
    int v[4], ts = 0;
#pragma unroll
    for (int u = 0; u < 4; u++) {
        int i = base + u;
        v[u] = (i < NH) ? g_icnt[i] : 0;
        ts += v[u];
    }
    int incl = ts;
#pragma unroll
    for (int o = 1; o < 32; o <<= 1) {
        int n = __shfl_up_sync(~0u, incl, o);
        if (lane >= o) incl += n;
    }
    __shared__ int wtot[16], woff[16];
    if (lane == 31) wtot[wid] = incl;
    __syncthreads();
    if (tid == 0) {
        int run = 0;
        for (int w = 0; w < 16; w++) { int t = wtot[w]; woff[w] = run; run += t; }
    }
    __syncthreads();
    int pre = g_bsum[blockIdx.x] + woff[wid] + (incl - ts);
#pragma unroll
    for (int u = 0; u < 4; u++) {
        int i = base + u;
        if (i < NH) { g_istart[i] = pre; g_icur[i] = pre; pre += v[u]; }
    }
}

__global__ void rank_kernel(const int* __restrict__ ih, const int* __restrict__ jl,
                            const int* __restrict__ kc, int E, int Nlow) {
    int e = blockIdx.x * blockDim.x + threadIdx.x;
    if (e >= E) return;
    int rank = atomicAdd(&g_icur[ih[e]], 1);
    g_jk[rank] = kc[e] * Nlow + jl[e];
}

// ---- GEMM: Y[k][n][co] = X @ W_k^T in fp16, k-loop with double-buffered W ----
#define STR 80                         // 64 data + 16 pad words; tg stride 20
#define AT_WORDS (128 * STR)           // 40 KB
#define SMEM_BYTES (3 * AT_WORDS * 4)  // 120 KB: A + 2x W

__global__ void __launch_bounds__(512, 1) gemm_kernel(int N) {
    extern __shared__ unsigned smem[];
    unsigned* As = smem;
    unsigned* Wb[2] = { smem + AT_WORDS, smem + 2 * AT_WORDS };
    const int tid = threadIdx.x;
    const int n0 = blockIdx.x * 128;

    unsigned sA = (unsigned)__cvta_generic_to_shared(As);
    unsigned sW[2] = { (unsigned)__cvta_generic_to_shared(Wb[0]),
                       (unsigned)__cvta_generic_to_shared(Wb[1]) };

    // stage: 512 threads, 128 rows -> thread (r=tid>>2, tg=tid&3), 4 uint4 each
    const int sr = tid >> 2, stg = tid & 3;
    {
        const unsigned* gx = g_xh + (size_t)(n0 + sr) * 64 + stg * 16;
        const unsigned* gw = g_wh + (size_t)sr * 64 + stg * 16;
        unsigned dA = sA + (sr * STR + stg * 20) * 4;
        unsigned dW = sW[0] + (sr * STR + stg * 20) * 4;
#pragma unroll
        for (int q = 0; q < 4; q++) {
            cpa16(dA + q * 16, gx + q * 4);
            cpa16(dW + q * 16, gw + q * 4);
        }
    }
    asm volatile("cp.async.commit_group;");
    {
        const unsigned* gw = g_wh + (size_t)(C * 64) + (size_t)sr * 64 + stg * 16;
        unsigned dW = sW[1] + (sr * STR + stg * 20) * 4;
#pragma unroll
        for (int q = 0; q < 4; q++)
            cpa16(dW + q * 16, gw + q * 4);
    }
    asm volatile("cp.async.commit_group;");

    const int warp = tid >> 5, lane = tid & 31;
    const int g = lane >> 2, tg = lane & 3;
    const int rowBase = (warp >> 2) * 32;
    const int coBase  = (warp & 3) * 32;

    const uint4* A0 = (const uint4*)(As + (rowBase + g     ) * STR + tg * 20);
    const uint4* A1 = (const uint4*)(As + (rowBase + g +  8) * STR + tg * 20);
    const uint4* A2 = (const uint4*)(As + (rowBase + g + 16) * STR + tg * 20);
    const uint4* A3 = (const uint4*)(As + (rowBase + g + 24) * STR + tg * 20);
    const int bOff = ((coBase + g) * STR + tg * 20) / 4;   // uint4 units
    const int ntStride = (8 * STR) / 4;

    for (int k = 0; k < KC; k++) {
        if (k < KC - 1) {
            asm volatile("cp.async.wait_group 1;" ::: "memory");
        } else {
            asm volatile("cp.async.wait_group 0;" ::: "memory");
        }
        __syncthreads();

        const uint4* Bp = (const uint4*)(Wb[k & 1]) + bOff;

        float acc[2][4][4];
#pragma unroll
        for (int mt = 0; mt < 2; mt++)
#pragma unroll
            for (int nt = 0; nt < 4; nt++) {
                acc[mt][nt][0] = 0.f; acc[mt][nt][1] = 0.f;
                acc[mt][nt][2] = 0.f; acc[mt][nt][3] = 0.f;
            }

#pragma unroll
        for (int q = 0; q < 4; q++) {         // 2 k16-steps per q
            uint4 a0 = A0[q];
            uint4 a1 = A1[q];
            uint4 a2 = A2[q];
            uint4 a3 = A3[q];
            uint4 b0 = Bp[0 * ntStride + q];
            uint4 b1 = Bp[1 * ntStride + q];
            uint4 b2 = Bp[2 * ntStride + q];
            uint4 b3 = Bp[3 * ntStride + q];
            // k16-step kb = 2q
            mma_f16(acc[0][0], a0.x, a1.x, a0.y, a1.y, b0.x, b0.y);
            mma_f16(acc[0][1], a0.x, a1.x, a0.y, a1.y, b1.x, b1.y);
            mma_f16(acc[0][2], a0.x, a1.x, a0.y, a1.y, b2.x, b2.y);
            mma_f16(acc[0][3], a0.x, a1.x, a0.y, a1.y, b3.x, b3.y);
            mma_f16(acc[1][0], a2.x, a3.x, a2.y, a3.y, b0.x, b0.y);
            mma_f16(acc[1][1], a2.x, a3.x, a2.y, a3.y, b1.x, b1.y);
            mma_f16(acc[1][2], a2.x, a3.x, a2.y, a3.y, b2.x, b2.y);
            mma_f16(acc[1][3], a2.x, a3.x, a2.y, a3.y, b3.x, b3.y);
            // k16-step kb = 2q+1
            mma_f16(acc[0][0], a0.z, a1.z, a0.w, a1.w, b0.z, b0.w);
            mma_f16(acc[0][1], a0.z, a1.z, a0.w, a1.w, b1.z, b1.w);
            mma_f16(acc[0][2], a0.z, a1.z, a0.w, a1.w, b2.z, b2.w);
            mma_f16(acc[0][3], a0.z, a1.z, a0.w, a1.w, b3.z, b3.w);
            mma_f16(acc[1][0], a2.z, a3.z, a2.w, a3.w, b0.z, b0.w);
            mma_f16(acc[1][1], a2.z, a3.z, a2.w, a3.w, b1.z, b1.w);
            mma_f16(acc[1][2], a2.z, a3.z, a2.w, a3.w, b2.z, b2.w);
            mma_f16(acc[1][3], a2.z, a3.z, a2.w, a3.w, b3.z, b3.w);
        }

        // epilogue: Y in fp16
        __half2* Yk = g_y2 + (size_t)k * N * 64;
#pragma unroll
        for (int mt = 0; mt < 2; mt++) {
            int r0 = n0 + rowBase + mt * 16 + g;
#pragma unroll
            for (int nt = 0; nt < 4; nt++) {
                int co2 = (coBase + nt * 8 + 2 * tg) >> 1;
                if (r0 < N)
                    Yk[(size_t)r0 * 64 + co2] =
                        __float22half2_rn(make_float2(acc[mt][nt][0], acc[mt][nt][1]));
                if (r0 + 8 < N)
                    Yk[(size_t)(r0 + 8) * 64 + co2] =
                        __float22half2_rn(make_float2(acc[mt][nt][2], acc[mt][nt][3]));
            }
        }
        __syncthreads();

        // prefetch W[k+2] into the buffer we just finished reading
        if (k + 2 < KC) {
            const unsigned* gw = g_wh + (size_t)(k + 2) * (C * 64) + (size_t)sr * 64 + stg * 16;
            unsigned dW = sW[k & 1] + (sr * STR + stg * 20) * 4;
#pragma unroll
            for (int q = 0; q < 4; q++)
                cpa16(dW + q * 16, gw + q * 4);
        }
        asm volatile("cp.async.commit_group;");
    }
}

// ---- segmented sum: warp per output row, plain gathers, no atomics ----
__global__ void segsum_kernel(float* __restrict__ out, const float* __restrict__ bias,
                              int NH) {
    int gw = (blockIdx.x * blockDim.x + threadIdx.x) >> 5;
    int lane = threadIdx.x & 31;
    if (gw >= NH) return;
    int start = g_istart[gw];
    int cnt = g_icnt[gw];
    float4 acc = ((const float4*)bias)[lane];
    const char* ybase = (const char*)g_y2;
    int r = 0;
    for (; r + 2 <= cnt; r += 2) {
        int jk0 = g_jk[start + r];
        int jk1 = g_jk[start + r + 1];
        uint2 v0 = *(const uint2*)(ybase + (size_t)jk0 * 256 + lane * 8);
        uint2 v1 = *(const uint2*)(ybase + (size_t)jk1 * 256 + lane * 8);
        float2 a = __half22float2(*(const __half2*)&v0.x);
        float2 b = __half22float2(*(const __half2*)&v0.y);
        float2 c = __half22float2(*(const __half2*)&v1.x);
        float2 d = __half22float2(*(const __half2*)&v1.y);
        acc.x += a.x + c.x; acc.y += a.y + c.y;
        acc.z += b.x + d.x; acc.w += b.y + d.y;
    }
    if (r < cnt) {
        int jk0 = g_jk[start + r];
        uint2 v0 = *(const uint2*)(ybase + (size_t)jk0 * 256 + lane * 8);
        float2 a = __half22float2(*(const __half2*)&v0.x);
        float2 b = __half22float2(*(const __half2*)&v0.y);
        acc.x += a.x; acc.y += a.y; acc.z += b.x; acc.w += b.y;
    }
    ((float4*)out)[(size_t)gw * 32 + lane] = acc;
}

extern "C" void kernel_launch(void* const* d_in, const int* in_sizes, int n_in,
                              void* d_out, int out_size) {
    const float* x    = (const float*)d_in[0];
    const float* w    = (const float*)d_in[1];
    const float* bias = (const float*)d_in[2];
    const int* ih     = (const int*)d_in[3];
    const int* jl     = (const int*)d_in[4];
    const int* kc     = (const int*)d_in[5];
    float* out = (float*)d_out;

    const int Nlow = in_sizes[0] / C;          // 50000
    const int E    = in_sizes[3];              // 1,000,000
    const int NH   = out_size / C;             // 200,000
    const int nbScan = (NH + SCAN_ELEMS - 1) / SCAN_ELEMS;
    const int nTiles = (Nlow + 127) / 128;

    pack_x_kernel<<<(Nlow * 64 + 255) / 256, 256>>>(x, Nlow);          // 0
    pack_w_kernel<<<(KC * C * 64 + 255) / 256, 256>>>(w);              // 1
    zinit_kernel<<<(NH + 255) / 256, 256>>>(NH);                       // 2
    hist_kernel<<<512, 256>>>(ih, E);                                  // 3
    scan1_kernel<<<nbScan, 512>>>(NH);                                 // 4

    cudaFuncSetAttribute(gemm_kernel, cudaFuncAttributeMaxDynamicSharedMemorySize,
                         SMEM_BYTES);
    gemm_kernel<<<nTiles, 512, SMEM_BYTES>>>(Nlow);                    // 5 (ncu target)

    scan2_kernel<<<1, 128>>>(nbScan);                                  // 6
    scan3_kernel<<<nbScan, 512>>>(NH);                                 // 7
    rank_kernel<<<(E + 255) / 256, 256>>>(ih, jl, kc, E, Nlow);        // 8

    long long sthreads = (long long)NH * 32;
    segsum_kernel<<<(int)((sthreads + 255) / 256), 256>>>(out, bias, NH);  // 9
}